// round 1
// baseline (speedup 1.0000x reference)
#include <cuda_runtime.h>
#include <math.h>

#define D       128
#define NMAX    100000
#define EMAX    1600000
#define NGRAPH  64
#define NEG_SLOPE 0.2f

// ---------------- scratch (static device globals; no allocation) ------------
__device__ float g_bufA[(size_t)NMAX * D];   // feat buffer (51.2 MB)
__device__ float g_bufB[(size_t)NMAX * D];   // aggregation buffer (51.2 MB)
__device__ float g_el[NMAX];
__device__ float g_er[NMAX];
__device__ float g_m[NMAX];
__device__ float g_s[NMAX];
__device__ float g_e[EMAX];
__device__ float g_acc[NGRAPH * 2];
__device__ float g_cnt[NGRAPH];

// ---------------- GEMM: out[N,128] = act(X)[N,128] @ W[128,128] -------------
// act(X) = preRelu ? relu(X + preBias) : X   (applied on load)
// Block: 256 threads, tile 64 rows x 128 cols. W fully staged (64KB smem),
// X tile staged k-major (Xs[k][row], 32KB) for conflict-free float4 reads.
#define GEMM_SMEM ((D * D + D * 64) * (int)sizeof(float))

__global__ void gemm_kernel(const float* __restrict__ X,
                            const float* __restrict__ W,
                            const float* __restrict__ preBias, int preRelu,
                            float* __restrict__ out, int N) {
    extern __shared__ float sm[];
    float* Ws = sm;            // [128][128]
    float* Xs = sm + D * D;    // [128][64] (k-major)
    const int tx   = threadIdx.x;
    const int row0 = blockIdx.x * 64;

    // stage W (16384 floats, float4-coalesced)
    for (int idx = tx * 4; idx < D * D; idx += 256 * 4)
        *(float4*)&Ws[idx] = *(const float4*)&W[idx];

    // stage X tile transposed: thread -> (row r, 32-wide k chunk)
    {
        int r    = tx >> 2;           // 0..63
        int k0   = (tx & 3) * 32;     // 0,32,64,96
        int grow = row0 + r;
        if (grow < N) {
            const float* xr = X + (size_t)grow * D + k0;
#pragma unroll
            for (int kk = 0; kk < 32; kk += 4) {
                float4 v = *(const float4*)&xr[kk];
                if (preRelu) {
                    float4 b = *(const float4*)&preBias[k0 + kk];
                    v.x = fmaxf(v.x + b.x, 0.f);
                    v.y = fmaxf(v.y + b.y, 0.f);
                    v.z = fmaxf(v.z + b.z, 0.f);
                    v.w = fmaxf(v.w + b.w, 0.f);
                }
                Xs[(k0 + kk + 0) * 64 + r] = v.x;
                Xs[(k0 + kk + 1) * 64 + r] = v.y;
                Xs[(k0 + kk + 2) * 64 + r] = v.z;
                Xs[(k0 + kk + 3) * 64 + r] = v.w;
            }
        } else {
#pragma unroll
            for (int kk = 0; kk < 32; kk++) Xs[(k0 + kk) * 64 + r] = 0.f;
        }
    }
    __syncthreads();

    const int tc = (tx & 15) * 8;   // col group (8 contiguous cols)
    const int tr = (tx >> 4) * 4;   // row group (4 contiguous rows)
    float acc[4][8];
#pragma unroll
    for (int i = 0; i < 4; i++)
#pragma unroll
        for (int j = 0; j < 8; j++) acc[i][j] = 0.f;

#pragma unroll 2
    for (int k = 0; k < D; k++) {
        float4 xv = *(const float4*)&Xs[k * 64 + tr];
        float4 wa = *(const float4*)&Ws[k * D + tc];
        float4 wb = *(const float4*)&Ws[k * D + tc + 4];
        float xr[4] = {xv.x, xv.y, xv.z, xv.w};
        float wr[8] = {wa.x, wa.y, wa.z, wa.w, wb.x, wb.y, wb.z, wb.w};
#pragma unroll
        for (int i = 0; i < 4; i++)
#pragma unroll
            for (int j = 0; j < 8; j++)
                acc[i][j] = fmaf(xr[i], wr[j], acc[i][j]);
    }

#pragma unroll
    for (int i = 0; i < 4; i++) {
        int grow = row0 + tr + i;
        if (grow < N) {
            float4 o0 = make_float4(acc[i][0], acc[i][1], acc[i][2], acc[i][3]);
            float4 o1 = make_float4(acc[i][4], acc[i][5], acc[i][6], acc[i][7]);
            *(float4*)&out[(size_t)grow * D + tc]     = o0;
            *(float4*)&out[(size_t)grow * D + tc + 4] = o1;
        }
    }
}

// ---------------- el/er = feat @ a_l, feat @ a_r (warp per row) -------------
__global__ void rowdot_kernel(const float* __restrict__ feat,
                              const float* __restrict__ al,
                              const float* __restrict__ ar,
                              float* __restrict__ el, float* __restrict__ er,
                              int N) {
    int gtid = blockIdx.x * blockDim.x + threadIdx.x;
    int row  = gtid >> 5;
    int lane = gtid & 31;
    if (row >= N) return;
    float4 f = *(const float4*)&feat[(size_t)row * D + lane * 4];
    float4 a = *(const float4*)&al[lane * 4];
    float4 b = *(const float4*)&ar[lane * 4];
    float dl = f.x * a.x + f.y * a.y + f.z * a.z + f.w * a.w;
    float dr = f.x * b.x + f.y * b.y + f.z * b.z + f.w * b.w;
#pragma unroll
    for (int o = 16; o; o >>= 1) {
        dl += __shfl_xor_sync(0xffffffffu, dl, o);
        dr += __shfl_xor_sync(0xffffffffu, dr, o);
    }
    if (lane == 0) { el[row] = dl; er[row] = dr; }
}

// ---------------- init m = -inf, s = 0 --------------------------------------
__global__ void init_ms_kernel(float* __restrict__ m, float* __restrict__ s, int N) {
    int i = blockIdx.x * blockDim.x + threadIdx.x;
    if (i < N) { m[i] = -INFINITY; s[i] = 0.f; }
}

// ---------------- edge pass 1: e = leakyrelu(el[src]+er[dst]); segmax -------
__global__ void edge_max_kernel(const int* __restrict__ src, const int* __restrict__ dst,
                                const float* __restrict__ el, const float* __restrict__ er,
                                float* __restrict__ e, float* __restrict__ m, int E) {
    int i = blockIdx.x * blockDim.x + threadIdx.x;
    if (i >= E) return;
    int s = src[i], d = dst[i];
    float v = el[s] + er[d];
    v = v > 0.f ? v : NEG_SLOPE * v;
    e[i] = v;
    // float atomic max via int/uint trick (m initialized to -inf)
    if (v >= 0.f) atomicMax((int*)&m[d], __float_as_int(v));
    else          atomicMin((unsigned int*)&m[d], __float_as_uint(v));
}

// ---------------- edge pass 2: ex = exp(e - m[dst]); segsum -> s ------------
__global__ void edge_exp_kernel(const int* __restrict__ dst,
                                const float* __restrict__ m,
                                float* __restrict__ e, float* __restrict__ s, int E) {
    int i = blockIdx.x * blockDim.x + threadIdx.x;
    if (i >= E) return;
    int d = dst[i];
    float ex = expf(e[i] - m[d]);
    e[i] = ex;
    atomicAdd(&s[d], ex);
}

// ---------------- edge pass 3: out[dst] += alpha * feat[src] (warp/edge) ----
__global__ void edge_agg_kernel(const int* __restrict__ src, const int* __restrict__ dst,
                                const float* __restrict__ ex, const float* __restrict__ ssum,
                                const float* __restrict__ feat, float* __restrict__ out,
                                int E) {
    int gtid = blockIdx.x * blockDim.x + threadIdx.x;
    int eid  = gtid >> 5;
    int lane = gtid & 31;
    if (eid >= E) return;
    int s = src[eid], d = dst[eid];
    float alpha = ex[eid] / ssum[d];
    float4 v = *(const float4*)&feat[(size_t)s * D + lane * 4];
    float* p = &out[(size_t)d * D + lane * 4];
    asm volatile("red.global.add.v4.f32 [%0], {%1, %2, %3, %4};"
                 :: "l"(p), "f"(v.x * alpha), "f"(v.y * alpha),
                    "f"(v.z * alpha), "f"(v.w * alpha)
                 : "memory");
}

// ---------------- pooling fused with FC: acc[g,c] += relu(x+b2).Wfc[:,c] ----
__global__ void pool_kernel(const float* __restrict__ x,
                            const float* __restrict__ b2,
                            const float* __restrict__ Wfc,
                            const int* __restrict__ gid,
                            float* __restrict__ acc, float* __restrict__ cnt, int N) {
    int gtid = blockIdx.x * blockDim.x + threadIdx.x;
    int row  = gtid >> 5;
    int lane = gtid & 31;
    if (row >= N) return;
    float4 v = *(const float4*)&x[(size_t)row * D + lane * 4];
    float4 b = *(const float4*)&b2[lane * 4];
    float x0 = fmaxf(v.x + b.x, 0.f);
    float x1 = fmaxf(v.y + b.y, 0.f);
    float x2 = fmaxf(v.z + b.z, 0.f);
    float x3 = fmaxf(v.w + b.w, 0.f);
    // Wfc is [128,2] row-major -> 8 consecutive floats cover this lane's 4 k's
    float4 w01 = *(const float4*)&Wfc[lane * 8];
    float4 w23 = *(const float4*)&Wfc[lane * 8 + 4];
    float d0 = x0 * w01.x + x1 * w01.z + x2 * w23.x + x3 * w23.z;
    float d1 = x0 * w01.y + x1 * w01.w + x2 * w23.y + x3 * w23.w;
#pragma unroll
    for (int o = 16; o; o >>= 1) {
        d0 += __shfl_xor_sync(0xffffffffu, d0, o);
        d1 += __shfl_xor_sync(0xffffffffu, d1, o);
    }
    if (lane == 0) {
        int g = gid[row];
        atomicAdd(&acc[g * 2 + 0], d0);
        atomicAdd(&acc[g * 2 + 1], d1);
        atomicAdd(&cnt[g], 1.f);
    }
}

// ---------------- finalize: mean, +bfc, log_softmax -------------------------
__global__ void finalize_kernel(const float* __restrict__ acc,
                                const float* __restrict__ cnt,
                                const float* __restrict__ bfc,
                                float* __restrict__ out) {
    int g = threadIdx.x;
    if (g >= NGRAPH) return;
    float c  = fmaxf(cnt[g], 1.f);
    float l0 = acc[g * 2 + 0] / c + bfc[0];
    float l1 = acc[g * 2 + 1] / c + bfc[1];
    float mx  = fmaxf(l0, l1);
    float lse = mx + logf(expf(l0 - mx) + expf(l1 - mx));
    out[g * 2 + 0] = l0 - lse;
    out[g * 2 + 1] = l1 - lse;
}

// ---------------- launch --------------------------------------------------
extern "C" void kernel_launch(void* const* d_in, const int* in_sizes, int n_in,
                              void* d_out, int out_size) {
    const float* h   = (const float*)d_in[0];
    const int*   src = (const int*)d_in[1];
    const int*   dst = (const int*)d_in[2];
    const int*   gid = (const int*)d_in[3];
    const float* W1  = (const float*)d_in[4];
    const float* al1 = (const float*)d_in[5];
    const float* ar1 = (const float*)d_in[6];
    const float* b1  = (const float*)d_in[7];
    const float* W2  = (const float*)d_in[8];
    const float* al2 = (const float*)d_in[9];
    const float* ar2 = (const float*)d_in[10];
    const float* b2  = (const float*)d_in[11];
    const float* Wfc = (const float*)d_in[12];
    const float* bfc = (const float*)d_in[13];

    const int N = in_sizes[0] / D;
    const int E = in_sizes[1];

    float *bufA, *bufB, *el, *er, *m, *s, *e, *acc, *cnt;
    cudaGetSymbolAddress((void**)&bufA, g_bufA);
    cudaGetSymbolAddress((void**)&bufB, g_bufB);
    cudaGetSymbolAddress((void**)&el,   g_el);
    cudaGetSymbolAddress((void**)&er,   g_er);
    cudaGetSymbolAddress((void**)&m,    g_m);
    cudaGetSymbolAddress((void**)&s,    g_s);
    cudaGetSymbolAddress((void**)&e,    g_e);
    cudaGetSymbolAddress((void**)&acc,  g_acc);
    cudaGetSymbolAddress((void**)&cnt,  g_cnt);

    cudaFuncSetAttribute(gemm_kernel, cudaFuncAttributeMaxDynamicSharedMemorySize,
                         GEMM_SMEM);

    const int TPB = 256;
    const int nBlocks     = (N + TPB - 1) / TPB;
    const int nWarpBlocks = (N * 32 + TPB - 1) / TPB;
    const int eBlocks     = (E + TPB - 1) / TPB;
    const int eWarpBlocks = (E * 32 + TPB - 1) / TPB;   // 51.2M threads, fits int
    const int gemmBlocks  = (N + 63) / 64;

    // ---------------- layer 1 ----------------
    cudaMemsetAsync(bufB, 0, (size_t)N * D * sizeof(float), 0);
    init_ms_kernel<<<nBlocks, TPB>>>(m, s, N);
    gemm_kernel<<<gemmBlocks, TPB, GEMM_SMEM>>>(h, W1, nullptr, 0, bufA, N);
    rowdot_kernel<<<nWarpBlocks, TPB>>>(bufA, al1, ar1, el, er, N);
    edge_max_kernel<<<eBlocks, TPB>>>(src, dst, el, er, e, m, E);
    edge_exp_kernel<<<eBlocks, TPB>>>(dst, m, e, s, E);
    edge_agg_kernel<<<eWarpBlocks, TPB>>>(src, dst, e, s, bufA, bufB, E);

    // ---------------- layer 2 ----------------
    // gemm reads relu(bufB + b1) -> bufA; bufB then reused as the new out buf
    gemm_kernel<<<gemmBlocks, TPB, GEMM_SMEM>>>(bufB, W2, b1, 1, bufA, N);
    init_ms_kernel<<<nBlocks, TPB>>>(m, s, N);
    rowdot_kernel<<<nWarpBlocks, TPB>>>(bufA, al2, ar2, el, er, N);
    edge_max_kernel<<<eBlocks, TPB>>>(src, dst, el, er, e, m, E);
    edge_exp_kernel<<<eBlocks, TPB>>>(dst, m, e, s, E);
    cudaMemsetAsync(bufB, 0, (size_t)N * D * sizeof(float), 0);
    edge_agg_kernel<<<eWarpBlocks, TPB>>>(src, dst, e, s, bufA, bufB, E);

    // ---------------- pool + FC + log_softmax ----------------
    cudaMemsetAsync(acc, 0, NGRAPH * 2 * sizeof(float), 0);
    cudaMemsetAsync(cnt, 0, NGRAPH * sizeof(float), 0);
    pool_kernel<<<nWarpBlocks, TPB>>>(bufB, b2, Wfc, gid, acc, cnt, N);
    finalize_kernel<<<1, 64>>>(acc, cnt, bfc, (float*)d_out);
}

// round 2
// speedup vs baseline: 1.3035x; 1.3035x over previous
#include <cuda_runtime.h>
#include <math.h>

#define D       128
#define NMAX    100000
#define EMAX    1600000
#define NGRAPH  64
#define NEG_SLOPE 0.2f

// ---------------- scratch (static device globals; no allocation) ------------
__device__ float g_bufA[(size_t)NMAX * D];   // feat buffer (51.2 MB)
__device__ float g_bufB[(size_t)NMAX * D];   // aggregation output (51.2 MB)
__device__ float g_el[NMAX];
__device__ float g_er[NMAX];
__device__ float g_e[EMAX];                  // per-edge scratch (CSR order)
__device__ int   g_cnt[NMAX];
__device__ int   g_rowptr[NMAX + 1];
__device__ int   g_cursor[NMAX];
__device__ int   g_col[EMAX];                // src ids sorted by dst
__device__ float g_acc[NGRAPH * 2];
__device__ float g_gcnt[NGRAPH];

// ================= CSR build =================
__global__ void hist_kernel(const int* __restrict__ dst, int* __restrict__ cnt, int E) {
    int i = blockIdx.x * blockDim.x + threadIdx.x;
    if (i < E) atomicAdd(&cnt[dst[i]], 1);
}

// single block, 1024 threads: exclusive scan of cnt[0..N) -> rowptr, cursor
__global__ void scan_kernel(const int* __restrict__ cnt, int* __restrict__ rowptr,
                            int* __restrict__ cursor, int N) {
    __shared__ int wsum[32];
    int t = threadIdx.x;
    int chunk = (N + 1023) >> 10;
    int b = t * chunk; if (b > N) b = N;
    int e = b + chunk; if (e > N) e = N;
    int sum = 0;
    for (int i = b; i < e; i++) sum += cnt[i];
    int lane = t & 31, w = t >> 5;
    int v = sum;
#pragma unroll
    for (int o = 1; o < 32; o <<= 1) {
        int u = __shfl_up_sync(0xffffffffu, v, o);
        if (lane >= o) v += u;
    }
    if (lane == 31) wsum[w] = v;
    __syncthreads();
    if (w == 0) {
        int x = wsum[lane];
#pragma unroll
        for (int o = 1; o < 32; o <<= 1) {
            int u = __shfl_up_sync(0xffffffffu, x, o);
            if (lane >= o) x += u;
        }
        wsum[lane] = x;
    }
    __syncthreads();
    int run = v - sum + (w > 0 ? wsum[w - 1] : 0);
    for (int i = b; i < e; i++) {
        rowptr[i] = run; cursor[i] = run;
        run += cnt[i];
    }
    if (b < N && e == N) rowptr[N] = run;
}

__global__ void scatter_kernel(const int* __restrict__ src, const int* __restrict__ dst,
                               int* __restrict__ cursor, int* __restrict__ col, int E) {
    int i = blockIdx.x * blockDim.x + threadIdx.x;
    if (i < E) {
        int p = atomicAdd(&cursor[dst[i]], 1);
        col[p] = src[i];
    }
}

// ================= GEMM: out[N,128] = act(X)[N,128] @ W[128,128] =============
// act(X) = preRelu ? relu(X + preBias) : X
// 256 thr, tile 64 rows x 128 cols, FFMA2 (fma.rn.f32x2) mainloop.
#define GEMM_SMEM ((D * D + D * 64) * (int)sizeof(float))

__global__ void gemm_kernel(const float* __restrict__ X,
                            const float* __restrict__ W,
                            const float* __restrict__ preBias, int preRelu,
                            float* __restrict__ out, int N) {
    extern __shared__ float sm[];
    float* Ws = sm;            // [128][128]
    float* Xs = sm + D * D;    // [128][64] k-major
    const int tx   = threadIdx.x;
    const int row0 = blockIdx.x * 64;

    for (int idx = tx * 4; idx < D * D; idx += 256 * 4)
        *(float4*)&Ws[idx] = *(const float4*)&W[idx];

    {
        int r    = tx >> 2;
        int k0   = (tx & 3) * 32;
        int grow = row0 + r;
        if (grow < N) {
            const float* xr = X + (size_t)grow * D + k0;
#pragma unroll
            for (int kk = 0; kk < 32; kk += 4) {
                float4 v = *(const float4*)&xr[kk];
                if (preRelu) {
                    float4 b = *(const float4*)&preBias[k0 + kk];
                    v.x = fmaxf(v.x + b.x, 0.f);
                    v.y = fmaxf(v.y + b.y, 0.f);
                    v.z = fmaxf(v.z + b.z, 0.f);
                    v.w = fmaxf(v.w + b.w, 0.f);
                }
                Xs[(k0 + kk + 0) * 64 + r] = v.x;
                Xs[(k0 + kk + 1) * 64 + r] = v.y;
                Xs[(k0 + kk + 2) * 64 + r] = v.z;
                Xs[(k0 + kk + 3) * 64 + r] = v.w;
            }
        } else {
#pragma unroll
            for (int kk = 0; kk < 32; kk++) Xs[(k0 + kk) * 64 + r] = 0.f;
        }
    }
    __syncthreads();

    const int tc = (tx & 15) * 8;   // 8 contiguous cols -> 4 f32x2 pairs
    const int tr = (tx >> 4) * 4;   // 4 contiguous rows
    unsigned long long acc[4][4];
#pragma unroll
    for (int i = 0; i < 4; i++)
#pragma unroll
        for (int j = 0; j < 4; j++) acc[i][j] = 0ull;

#pragma unroll 4
    for (int k = 0; k < D; k++) {
        float4 xv = *(const float4*)&Xs[k * 64 + tr];
        const unsigned long long* wrow =
            (const unsigned long long*)&Ws[k * D + tc];
        unsigned long long w0 = wrow[0], w1 = wrow[1], w2 = wrow[2], w3 = wrow[3];
        unsigned long long xp[4];
        asm("mov.b64 %0, {%1, %1};" : "=l"(xp[0]) : "f"(xv.x));
        asm("mov.b64 %0, {%1, %1};" : "=l"(xp[1]) : "f"(xv.y));
        asm("mov.b64 %0, {%1, %1};" : "=l"(xp[2]) : "f"(xv.z));
        asm("mov.b64 %0, {%1, %1};" : "=l"(xp[3]) : "f"(xv.w));
#pragma unroll
        for (int i = 0; i < 4; i++) {
            asm("fma.rn.f32x2 %0, %1, %2, %0;" : "+l"(acc[i][0]) : "l"(xp[i]), "l"(w0));
            asm("fma.rn.f32x2 %0, %1, %2, %0;" : "+l"(acc[i][1]) : "l"(xp[i]), "l"(w1));
            asm("fma.rn.f32x2 %0, %1, %2, %0;" : "+l"(acc[i][2]) : "l"(xp[i]), "l"(w2));
            asm("fma.rn.f32x2 %0, %1, %2, %0;" : "+l"(acc[i][3]) : "l"(xp[i]), "l"(w3));
        }
    }

#pragma unroll
    for (int i = 0; i < 4; i++) {
        int grow = row0 + tr + i;
        if (grow < N) {
            float o[8];
#pragma unroll
            for (int j = 0; j < 4; j++)
                asm("mov.b64 {%0, %1}, %2;" : "=f"(o[2 * j]), "=f"(o[2 * j + 1]) : "l"(acc[i][j]));
            *(float4*)&out[(size_t)grow * D + tc]     = make_float4(o[0], o[1], o[2], o[3]);
            *(float4*)&out[(size_t)grow * D + tc + 4] = make_float4(o[4], o[5], o[6], o[7]);
        }
    }
}

// ================= el/er = feat @ a_l, feat @ a_r (warp per row) =============
__global__ void rowdot_kernel(const float* __restrict__ feat,
                              const float* __restrict__ al,
                              const float* __restrict__ ar,
                              float* __restrict__ el, float* __restrict__ er,
                              int N) {
    int gtid = blockIdx.x * blockDim.x + threadIdx.x;
    int row  = gtid >> 5;
    int lane = gtid & 31;
    if (row >= N) return;
    float4 f = *(const float4*)&feat[(size_t)row * D + lane * 4];
    float4 a = *(const float4*)&al[lane * 4];
    float4 b = *(const float4*)&ar[lane * 4];
    float dl = f.x * a.x + f.y * a.y + f.z * a.z + f.w * a.w;
    float dr = f.x * b.x + f.y * b.y + f.z * b.z + f.w * b.w;
#pragma unroll
    for (int o = 16; o; o >>= 1) {
        dl += __shfl_xor_sync(0xffffffffu, dl, o);
        dr += __shfl_xor_sync(0xffffffffu, dr, o);
    }
    if (lane == 0) { el[row] = dl; er[row] = dr; }
}

// ========== fused per-dst edge softmax + aggregation (warp per dst) =========
__global__ void agg_kernel(const int* __restrict__ rowptr, const int* __restrict__ col,
                           const float* __restrict__ el, const float* __restrict__ er,
                           const float* __restrict__ feat, float* __restrict__ ebuf,
                           float* __restrict__ out, int N) {
    int node = (blockIdx.x * blockDim.x + threadIdx.x) >> 5;
    int lane = threadIdx.x & 31;
    if (node >= N) return;
    int beg = rowptr[node], end = rowptr[node + 1];
    float a0 = 0.f, a1 = 0.f, a2 = 0.f, a3 = 0.f;
    if (end > beg) {
        float erd = er[node];
        // pass A: e = leakyrelu(el[src]+er[dst]), warp max (lanes over edges)
        float mx = -INFINITY;
        for (int i = beg + lane; i < end; i += 32) {
            float v = el[col[i]] + erd;
            v = v > 0.f ? v : NEG_SLOPE * v;
            ebuf[i] = v;
            mx = fmaxf(mx, v);
        }
#pragma unroll
        for (int o = 16; o; o >>= 1)
            mx = fmaxf(mx, __shfl_xor_sync(0xffffffffu, mx, o));
        // pass B: ex = exp(e - mx), warp sum
        float s = 0.f;
        for (int i = beg + lane; i < end; i += 32) {
            float ex = __expf(ebuf[i] - mx);
            ebuf[i] = ex;
            s += ex;
        }
#pragma unroll
        for (int o = 16; o; o >>= 1)
            s += __shfl_xor_sync(0xffffffffu, s, o);
        float inv = 1.0f / s;
        // pass C: serial over edges, lanes over D; 2 edges in flight
        for (int base = beg; base < end; base += 32) {
            int rem = end - base;
            int cnt = rem < 32 ? rem : 32;
            int   myi = 0; float mye = 0.f;
            if (lane < cnt) { myi = col[base + lane]; mye = ebuf[base + lane]; }
            int j = 0;
            for (; j + 1 < cnt; j += 2) {
                int   sA = __shfl_sync(0xffffffffu, myi, j);
                float wA = __shfl_sync(0xffffffffu, mye, j) * inv;
                int   sB = __shfl_sync(0xffffffffu, myi, j + 1);
                float wB = __shfl_sync(0xffffffffu, mye, j + 1) * inv;
                float4 fA = *(const float4*)&feat[(size_t)sA * D + lane * 4];
                float4 fB = *(const float4*)&feat[(size_t)sB * D + lane * 4];
                a0 = fmaf(wA, fA.x, a0); a1 = fmaf(wA, fA.y, a1);
                a2 = fmaf(wA, fA.z, a2); a3 = fmaf(wA, fA.w, a3);
                a0 = fmaf(wB, fB.x, a0); a1 = fmaf(wB, fB.y, a1);
                a2 = fmaf(wB, fB.z, a2); a3 = fmaf(wB, fB.w, a3);
            }
            if (j < cnt) {
                int   sA = __shfl_sync(0xffffffffu, myi, j);
                float wA = __shfl_sync(0xffffffffu, mye, j) * inv;
                float4 fA = *(const float4*)&feat[(size_t)sA * D + lane * 4];
                a0 = fmaf(wA, fA.x, a0); a1 = fmaf(wA, fA.y, a1);
                a2 = fmaf(wA, fA.z, a2); a3 = fmaf(wA, fA.w, a3);
            }
        }
    }
    *(float4*)&out[(size_t)node * D + lane * 4] = make_float4(a0, a1, a2, a3);
}

// ========== pooling fused with FC: acc[g,c] += relu(x+b2).Wfc[:,c] ==========
__global__ void pool_kernel(const float* __restrict__ x,
                            const float* __restrict__ b2,
                            const float* __restrict__ Wfc,
                            const int* __restrict__ gid,
                            float* __restrict__ acc, float* __restrict__ cnt, int N) {
    int gtid = blockIdx.x * blockDim.x + threadIdx.x;
    int row  = gtid >> 5;
    int lane = gtid & 31;
    if (row >= N) return;
    float4 v = *(const float4*)&x[(size_t)row * D + lane * 4];
    float4 b = *(const float4*)&b2[lane * 4];
    float x0 = fmaxf(v.x + b.x, 0.f);
    float x1 = fmaxf(v.y + b.y, 0.f);
    float x2 = fmaxf(v.z + b.z, 0.f);
    float x3 = fmaxf(v.w + b.w, 0.f);
    float4 w01 = *(const float4*)&Wfc[lane * 8];
    float4 w23 = *(const float4*)&Wfc[lane * 8 + 4];
    float d0 = x0 * w01.x + x1 * w01.z + x2 * w23.x + x3 * w23.z;
    float d1 = x0 * w01.y + x1 * w01.w + x2 * w23.y + x3 * w23.w;
#pragma unroll
    for (int o = 16; o; o >>= 1) {
        d0 += __shfl_xor_sync(0xffffffffu, d0, o);
        d1 += __shfl_xor_sync(0xffffffffu, d1, o);
    }
    if (lane == 0) {
        int g = gid[row];
        atomicAdd(&acc[g * 2 + 0], d0);
        atomicAdd(&acc[g * 2 + 1], d1);
        atomicAdd(&cnt[g], 1.f);
    }
}

// ========== finalize: mean, +bfc, log_softmax ==========
__global__ void finalize_kernel(const float* __restrict__ acc,
                                const float* __restrict__ cnt,
                                const float* __restrict__ bfc,
                                float* __restrict__ out) {
    int g = threadIdx.x;
    if (g >= NGRAPH) return;
    float c  = fmaxf(cnt[g], 1.f);
    float l0 = acc[g * 2 + 0] / c + bfc[0];
    float l1 = acc[g * 2 + 1] / c + bfc[1];
    float mx  = fmaxf(l0, l1);
    float lse = mx + logf(expf(l0 - mx) + expf(l1 - mx));
    out[g * 2 + 0] = l0 - lse;
    out[g * 2 + 1] = l1 - lse;
}

// ================= launch =================
extern "C" void kernel_launch(void* const* d_in, const int* in_sizes, int n_in,
                              void* d_out, int out_size) {
    const float* h   = (const float*)d_in[0];
    const int*   src = (const int*)d_in[1];
    const int*   dst = (const int*)d_in[2];
    const int*   gid = (const int*)d_in[3];
    const float* W1  = (const float*)d_in[4];
    const float* al1 = (const float*)d_in[5];
    const float* ar1 = (const float*)d_in[6];
    const float* b1  = (const float*)d_in[7];
    const float* W2  = (const float*)d_in[8];
    const float* al2 = (const float*)d_in[9];
    const float* ar2 = (const float*)d_in[10];
    const float* b2  = (const float*)d_in[11];
    const float* Wfc = (const float*)d_in[12];
    const float* bfc = (const float*)d_in[13];

    const int N = in_sizes[0] / D;
    const int E = in_sizes[1];

    float *bufA, *bufB, *el, *er, *ebuf, *acc, *gcnt;
    int *cnt, *rowptr, *cursor, *colv;
    cudaGetSymbolAddress((void**)&bufA,   g_bufA);
    cudaGetSymbolAddress((void**)&bufB,   g_bufB);
    cudaGetSymbolAddress((void**)&el,     g_el);
    cudaGetSymbolAddress((void**)&er,     g_er);
    cudaGetSymbolAddress((void**)&ebuf,   g_e);
    cudaGetSymbolAddress((void**)&cnt,    g_cnt);
    cudaGetSymbolAddress((void**)&rowptr, g_rowptr);
    cudaGetSymbolAddress((void**)&cursor, g_cursor);
    cudaGetSymbolAddress((void**)&colv,   g_col);
    cudaGetSymbolAddress((void**)&acc,    g_acc);
    cudaGetSymbolAddress((void**)&gcnt,   g_gcnt);

    cudaFuncSetAttribute(gemm_kernel, cudaFuncAttributeMaxDynamicSharedMemorySize,
                         GEMM_SMEM);

    const int TPB = 256;
    const int eBlocks     = (E + TPB - 1) / TPB;
    const int nWarpBlocks = (N * 32 + TPB - 1) / TPB;
    const int gemmBlocks  = (N + 63) / 64;

    // ---- CSR build (shared by both layers) ----
    cudaMemsetAsync(cnt, 0, (size_t)N * sizeof(int), 0);
    hist_kernel<<<eBlocks, TPB>>>(dst, cnt, E);
    scan_kernel<<<1, 1024>>>(cnt, rowptr, cursor, N);
    scatter_kernel<<<eBlocks, TPB>>>(src, dst, cursor, colv, E);

    // ---- layer 1 ----
    gemm_kernel<<<gemmBlocks, TPB, GEMM_SMEM>>>(h, W1, nullptr, 0, bufA, N);
    rowdot_kernel<<<nWarpBlocks, TPB>>>(bufA, al1, ar1, el, er, N);
    agg_kernel<<<nWarpBlocks, TPB>>>(rowptr, colv, el, er, bufA, ebuf, bufB, N);

    // ---- layer 2 ----
    gemm_kernel<<<gemmBlocks, TPB, GEMM_SMEM>>>(bufB, W2, b1, 1, bufA, N);
    rowdot_kernel<<<nWarpBlocks, TPB>>>(bufA, al2, ar2, el, er, N);
    agg_kernel<<<nWarpBlocks, TPB>>>(rowptr, colv, el, er, bufA, ebuf, bufB, N);

    // ---- pool + FC + log_softmax ----
    cudaMemsetAsync(acc, 0, NGRAPH * 2 * sizeof(float), 0);
    cudaMemsetAsync(gcnt, 0, NGRAPH * sizeof(float), 0);
    pool_kernel<<<nWarpBlocks, TPB>>>(bufB, b2, Wfc, gid, acc, gcnt, N);
    finalize_kernel<<<1, 64>>>(acc, gcnt, bfc, (float*)d_out);
}

// round 3
// speedup vs baseline: 1.5557x; 1.1935x over previous
#include <cuda_runtime.h>
#include <math.h>

#define D       128
#define NMAX    100000
#define EMAX    1600000
#define NGRAPH  64
#define NEG_SLOPE 0.2f
#define TILE_R  128

typedef unsigned long long u64;

// ---------------- scratch (static device globals; no allocation) ------------
__device__ float g_bufA[(size_t)NMAX * D];   // feat buffer (51.2 MB)
__device__ float g_bufB[(size_t)NMAX * D];   // aggregation output (51.2 MB)
__device__ float g_el[NMAX];
__device__ float g_er[NMAX];
__device__ float g_e[EMAX];                  // per-edge scratch (CSR order)
__device__ int   g_cnt[NMAX];
__device__ int   g_rowptr[NMAX + 1];
__device__ int   g_cursor[NMAX];
__device__ int   g_col[EMAX];                // src ids sorted by dst
__device__ float g_acc[NGRAPH * 2];
__device__ float g_gcnt[NGRAPH];

// ================= CSR build =================
__global__ void hist_kernel(const int* __restrict__ dst, int* __restrict__ cnt, int E) {
    int i = blockIdx.x * blockDim.x + threadIdx.x;
    if (i < E) atomicAdd(&cnt[dst[i]], 1);
}

__global__ void scan_kernel(const int* __restrict__ cnt, int* __restrict__ rowptr,
                            int* __restrict__ cursor, int N) {
    __shared__ int wsum[32];
    int t = threadIdx.x;
    int chunk = (N + 1023) >> 10;
    int b = t * chunk; if (b > N) b = N;
    int e = b + chunk; if (e > N) e = N;
    int sum = 0;
    for (int i = b; i < e; i++) sum += cnt[i];
    int lane = t & 31, w = t >> 5;
    int v = sum;
#pragma unroll
    for (int o = 1; o < 32; o <<= 1) {
        int u = __shfl_up_sync(0xffffffffu, v, o);
        if (lane >= o) v += u;
    }
    if (lane == 31) wsum[w] = v;
    __syncthreads();
    if (w == 0) {
        int x = wsum[lane];
#pragma unroll
        for (int o = 1; o < 32; o <<= 1) {
            int u = __shfl_up_sync(0xffffffffu, x, o);
            if (lane >= o) x += u;
        }
        wsum[lane] = x;
    }
    __syncthreads();
    int run = v - sum + (w > 0 ? wsum[w - 1] : 0);
    for (int i = b; i < e; i++) {
        rowptr[i] = run; cursor[i] = run;
        run += cnt[i];
    }
    if (b < N && e == N) rowptr[N] = run;
}

__global__ void scatter_kernel(const int* __restrict__ src, const int* __restrict__ dst,
                               int* __restrict__ cursor, int* __restrict__ col, int E) {
    int i = blockIdx.x * blockDim.x + threadIdx.x;
    if (i < E) {
        int p = atomicAdd(&cursor[dst[i]], 1);
        col[p] = src[i];
    }
}

// ====== GEMM: out = act(X) @ W ; fused el/er = out @ {al, ar} ===============
// 256 thr, tile 128 rows x 128 cols. Thread owns 8 rows x 4 column PAIRS at
// columns 2p + {0,32,64,96} (p = tx&15) -> conflict-free LDS.64 of W that is
// directly the f32x2 operand of fma.rn.f32x2.
#define GEMM_SMEM ((D * D + D * TILE_R) * (int)sizeof(float))

__global__ void __launch_bounds__(256, 1)
gemm_kernel(const float* __restrict__ X, const float* __restrict__ W,
            const float* __restrict__ preBias, int preRelu,
            const float* __restrict__ al, const float* __restrict__ ar,
            float* __restrict__ out, float* __restrict__ el,
            float* __restrict__ er, int N) {
    extern __shared__ float sm[];
    float* Ws = sm;            // [k][c] 128x128
    float* Xs = sm + D * D;    // [k][r] 128x128
    const int tx   = threadIdx.x;
    const int row0 = blockIdx.x * TILE_R;

    // stage W (16 float4 per thread, coalesced)
    for (int idx = tx * 4; idx < D * D; idx += 256 * 4)
        *(float4*)&Ws[idx] = *(const float4*)&W[idx];

    // stage X transposed: 2 threads per row, 64 k's each
    {
        int r    = tx >> 1;
        int k0   = (tx & 1) * 64;
        int grow = row0 + r;
        if (grow < N) {
            const float* xr = X + (size_t)grow * D + k0;
#pragma unroll
            for (int kk = 0; kk < 64; kk += 4) {
                float4 v = *(const float4*)&xr[kk];
                if (preRelu) {
                    float4 b = *(const float4*)&preBias[k0 + kk];
                    v.x = fmaxf(v.x + b.x, 0.f);
                    v.y = fmaxf(v.y + b.y, 0.f);
                    v.z = fmaxf(v.z + b.z, 0.f);
                    v.w = fmaxf(v.w + b.w, 0.f);
                }
                Xs[(k0 + kk + 0) * TILE_R + r] = v.x;
                Xs[(k0 + kk + 1) * TILE_R + r] = v.y;
                Xs[(k0 + kk + 2) * TILE_R + r] = v.z;
                Xs[(k0 + kk + 3) * TILE_R + r] = v.w;
            }
        } else {
#pragma unroll
            for (int kk = 0; kk < 64; kk++) Xs[(k0 + kk) * TILE_R + r] = 0.f;
        }
    }
    __syncthreads();

    const int p = tx & 15;    // column pair lane: cols 2p + {0,32,64,96}
    const int q = tx >> 4;    // rows q*8 .. q*8+7
    u64 acc[8][4];
#pragma unroll
    for (int i = 0; i < 8; i++)
#pragma unroll
        for (int j = 0; j < 4; j++) acc[i][j] = 0ull;

#pragma unroll 4
    for (int k = 0; k < D; k++) {
        float4 xa = *(const float4*)&Xs[k * TILE_R + q * 8];
        float4 xb = *(const float4*)&Xs[k * TILE_R + q * 8 + 4];
        const u64* wrow = (const u64*)&Ws[k * D];
        u64 w0 = wrow[p], w1 = wrow[p + 16], w2 = wrow[p + 32], w3 = wrow[p + 48];
        u64 xp[8];
        asm("mov.b64 %0, {%1, %1};" : "=l"(xp[0]) : "f"(xa.x));
        asm("mov.b64 %0, {%1, %1};" : "=l"(xp[1]) : "f"(xa.y));
        asm("mov.b64 %0, {%1, %1};" : "=l"(xp[2]) : "f"(xa.z));
        asm("mov.b64 %0, {%1, %1};" : "=l"(xp[3]) : "f"(xa.w));
        asm("mov.b64 %0, {%1, %1};" : "=l"(xp[4]) : "f"(xb.x));
        asm("mov.b64 %0, {%1, %1};" : "=l"(xp[5]) : "f"(xb.y));
        asm("mov.b64 %0, {%1, %1};" : "=l"(xp[6]) : "f"(xb.z));
        asm("mov.b64 %0, {%1, %1};" : "=l"(xp[7]) : "f"(xb.w));
#pragma unroll
        for (int i = 0; i < 8; i++) {
            asm("fma.rn.f32x2 %0, %1, %2, %0;" : "+l"(acc[i][0]) : "l"(xp[i]), "l"(w0));
            asm("fma.rn.f32x2 %0, %1, %2, %0;" : "+l"(acc[i][1]) : "l"(xp[i]), "l"(w1));
            asm("fma.rn.f32x2 %0, %1, %2, %0;" : "+l"(acc[i][2]) : "l"(xp[i]), "l"(w2));
            asm("fma.rn.f32x2 %0, %1, %2, %0;" : "+l"(acc[i][3]) : "l"(xp[i]), "l"(w3));
        }
    }

    // epilogue: store + fused el/er partial dots (reduce across 16 p-lanes)
    float2 la[4], ra[4];
#pragma unroll
    for (int t = 0; t < 4; t++) {
        la[t] = *(const float2*)&al[2 * p + 32 * t];
        ra[t] = *(const float2*)&ar[2 * p + 32 * t];
    }
#pragma unroll
    for (int i = 0; i < 8; i++) {
        int grow = row0 + q * 8 + i;
        float pl = 0.f, pr = 0.f;
        float o0, o1;
#pragma unroll
        for (int t = 0; t < 4; t++) {
            asm("mov.b64 {%0, %1}, %2;" : "=f"(o0), "=f"(o1) : "l"(acc[i][t]));
            pl += o0 * la[t].x + o1 * la[t].y;
            pr += o0 * ra[t].x + o1 * ra[t].y;
            if (grow < N)
                *(float2*)&out[(size_t)grow * D + 2 * p + 32 * t] = make_float2(o0, o1);
        }
#pragma unroll
        for (int o = 8; o; o >>= 1) {
            pl += __shfl_xor_sync(0xffffffffu, pl, o);
            pr += __shfl_xor_sync(0xffffffffu, pr, o);
        }
        if (p == 0 && grow < N) { el[grow] = pl; er[grow] = pr; }
    }
}

// ========== fused per-dst edge softmax + aggregation (warp per dst) =========
// doPool: instead of storing the node row, fold relu(x+b2) @ Wfc into per-
// graph accumulators (layer 2 output never materialized).
__global__ void agg_kernel(const int* __restrict__ rowptr, const int* __restrict__ col,
                           const float* __restrict__ el, const float* __restrict__ er,
                           const float* __restrict__ feat, float* __restrict__ ebuf,
                           float* __restrict__ out, int N, int doPool,
                           const float* __restrict__ b2, const float* __restrict__ Wfc,
                           const int* __restrict__ gid,
                           float* __restrict__ acc, float* __restrict__ gcnt) {
    int node = (blockIdx.x * blockDim.x + threadIdx.x) >> 5;
    int lane = threadIdx.x & 31;
    if (node >= N) return;
    int beg = rowptr[node], end = rowptr[node + 1];
    int deg = end - beg;
    float a0 = 0.f, a1 = 0.f, a2 = 0.f, a3 = 0.f;

    if (deg > 0) {
        float erd = er[node];
        int   myi = 0;
        float mye = 0.f;
        float inv;
        if (deg <= 32) {
            // register fast path: one edge per lane, no ebuf traffic
            float v = -INFINITY;
            if (lane < deg) {
                myi = col[beg + lane];
                float t = el[myi] + erd;
                v = t > 0.f ? t : NEG_SLOPE * t;
            }
            float mx = v;
#pragma unroll
            for (int o = 16; o; o >>= 1)
                mx = fmaxf(mx, __shfl_xor_sync(0xffffffffu, mx, o));
            mye = (lane < deg) ? __expf(v - mx) : 0.f;
            float s = mye;
#pragma unroll
            for (int o = 16; o; o >>= 1)
                s += __shfl_xor_sync(0xffffffffu, s, o);
            inv = 1.0f / s;
            // weighted gather, 4 edges in flight
            int j = 0;
            for (; j + 3 < deg; j += 4) {
                int   s0 = __shfl_sync(0xffffffffu, myi, j);
                int   s1 = __shfl_sync(0xffffffffu, myi, j + 1);
                int   s2 = __shfl_sync(0xffffffffu, myi, j + 2);
                int   s3 = __shfl_sync(0xffffffffu, myi, j + 3);
                float w0 = __shfl_sync(0xffffffffu, mye, j) * inv;
                float w1 = __shfl_sync(0xffffffffu, mye, j + 1) * inv;
                float w2 = __shfl_sync(0xffffffffu, mye, j + 2) * inv;
                float w3 = __shfl_sync(0xffffffffu, mye, j + 3) * inv;
                float4 f0 = *(const float4*)&feat[(size_t)s0 * D + lane * 4];
                float4 f1 = *(const float4*)&feat[(size_t)s1 * D + lane * 4];
                float4 f2 = *(const float4*)&feat[(size_t)s2 * D + lane * 4];
                float4 f3 = *(const float4*)&feat[(size_t)s3 * D + lane * 4];
                a0 = fmaf(w0, f0.x, a0); a1 = fmaf(w0, f0.y, a1);
                a2 = fmaf(w0, f0.z, a2); a3 = fmaf(w0, f0.w, a3);
                a0 = fmaf(w1, f1.x, a0); a1 = fmaf(w1, f1.y, a1);
                a2 = fmaf(w1, f1.z, a2); a3 = fmaf(w1, f1.w, a3);
                a0 = fmaf(w2, f2.x, a0); a1 = fmaf(w2, f2.y, a1);
                a2 = fmaf(w2, f2.z, a2); a3 = fmaf(w2, f2.w, a3);
                a0 = fmaf(w3, f3.x, a0); a1 = fmaf(w3, f3.y, a1);
                a2 = fmaf(w3, f3.z, a2); a3 = fmaf(w3, f3.w, a3);
            }
            for (; j < deg; j++) {
                int   sA = __shfl_sync(0xffffffffu, myi, j);
                float wA = __shfl_sync(0xffffffffu, mye, j) * inv;
                float4 fA = *(const float4*)&feat[(size_t)sA * D + lane * 4];
                a0 = fmaf(wA, fA.x, a0); a1 = fmaf(wA, fA.y, a1);
                a2 = fmaf(wA, fA.z, a2); a3 = fmaf(wA, fA.w, a3);
            }
        } else {
            // general path via ebuf
            float mx = -INFINITY;
            for (int i = beg + lane; i < end; i += 32) {
                float v = el[col[i]] + erd;
                v = v > 0.f ? v : NEG_SLOPE * v;
                ebuf[i] = v;
                mx = fmaxf(mx, v);
            }
#pragma unroll
            for (int o = 16; o; o >>= 1)
                mx = fmaxf(mx, __shfl_xor_sync(0xffffffffu, mx, o));
            float s = 0.f;
            for (int i = beg + lane; i < end; i += 32) {
                float ex = __expf(ebuf[i] - mx);
                ebuf[i] = ex;
                s += ex;
            }
#pragma unroll
            for (int o = 16; o; o >>= 1)
                s += __shfl_xor_sync(0xffffffffu, s, o);
            inv = 1.0f / s;
            for (int base = beg; base < end; base += 32) {
                int rem = end - base;
                int cnt = rem < 32 ? rem : 32;
                int mi = 0; float me = 0.f;
                if (lane < cnt) { mi = col[base + lane]; me = ebuf[base + lane]; }
                int j = 0;
                for (; j + 3 < cnt; j += 4) {
                    int   s0 = __shfl_sync(0xffffffffu, mi, j);
                    int   s1 = __shfl_sync(0xffffffffu, mi, j + 1);
                    int   s2 = __shfl_sync(0xffffffffu, mi, j + 2);
                    int   s3 = __shfl_sync(0xffffffffu, mi, j + 3);
                    float w0 = __shfl_sync(0xffffffffu, me, j) * inv;
                    float w1 = __shfl_sync(0xffffffffu, me, j + 1) * inv;
                    float w2 = __shfl_sync(0xffffffffu, me, j + 2) * inv;
                    float w3 = __shfl_sync(0xffffffffu, me, j + 3) * inv;
                    float4 f0 = *(const float4*)&feat[(size_t)s0 * D + lane * 4];
                    float4 f1 = *(const float4*)&feat[(size_t)s1 * D + lane * 4];
                    float4 f2 = *(const float4*)&feat[(size_t)s2 * D + lane * 4];
                    float4 f3 = *(const float4*)&feat[(size_t)s3 * D + lane * 4];
                    a0 = fmaf(w0, f0.x, a0); a1 = fmaf(w0, f0.y, a1);
                    a2 = fmaf(w0, f0.z, a2); a3 = fmaf(w0, f0.w, a3);
                    a0 = fmaf(w1, f1.x, a0); a1 = fmaf(w1, f1.y, a1);
                    a2 = fmaf(w1, f1.z, a2); a3 = fmaf(w1, f1.w, a3);
                    a0 = fmaf(w2, f2.x, a0); a1 = fmaf(w2, f2.y, a1);
                    a2 = fmaf(w2, f2.z, a2); a3 = fmaf(w2, f2.w, a3);
                    a0 = fmaf(w3, f3.x, a0); a1 = fmaf(w3, f3.y, a1);
                    a2 = fmaf(w3, f3.z, a2); a3 = fmaf(w3, f3.w, a3);
                }
                for (; j < cnt; j++) {
                    int   sA = __shfl_sync(0xffffffffu, mi, j);
                    float wA = __shfl_sync(0xffffffffu, me, j) * inv;
                    float4 fA = *(const float4*)&feat[(size_t)sA * D + lane * 4];
                    a0 = fmaf(wA, fA.x, a0); a1 = fmaf(wA, fA.y, a1);
                    a2 = fmaf(wA, fA.z, a2); a3 = fmaf(wA, fA.w, a3);
                }
            }
        }
    }

    if (!doPool) {
        *(float4*)&out[(size_t)node * D + lane * 4] = make_float4(a0, a1, a2, a3);
    } else {
        float4 b = *(const float4*)&b2[lane * 4];
        float x0 = fmaxf(a0 + b.x, 0.f);
        float x1 = fmaxf(a1 + b.y, 0.f);
        float x2 = fmaxf(a2 + b.z, 0.f);
        float x3 = fmaxf(a3 + b.w, 0.f);
        float4 w01 = *(const float4*)&Wfc[lane * 8];
        float4 w23 = *(const float4*)&Wfc[lane * 8 + 4];
        float d0 = x0 * w01.x + x1 * w01.z + x2 * w23.x + x3 * w23.z;
        float d1 = x0 * w01.y + x1 * w01.w + x2 * w23.y + x3 * w23.w;
#pragma unroll
        for (int o = 16; o; o >>= 1) {
            d0 += __shfl_xor_sync(0xffffffffu, d0, o);
            d1 += __shfl_xor_sync(0xffffffffu, d1, o);
        }
        if (lane == 0) {
            int g = gid[node];
            atomicAdd(&acc[g * 2 + 0], d0);
            atomicAdd(&acc[g * 2 + 1], d1);
            atomicAdd(&gcnt[g], 1.f);
        }
    }
}

// ========== finalize: mean, +bfc, log_softmax ==========
__global__ void finalize_kernel(const float* __restrict__ acc,
                                const float* __restrict__ cnt,
                                const float* __restrict__ bfc,
                                float* __restrict__ out) {
    int g = threadIdx.x;
    if (g >= NGRAPH) return;
    float c  = fmaxf(cnt[g], 1.f);
    float l0 = acc[g * 2 + 0] / c + bfc[0];
    float l1 = acc[g * 2 + 1] / c + bfc[1];
    float mx  = fmaxf(l0, l1);
    float lse = mx + logf(expf(l0 - mx) + expf(l1 - mx));
    out[g * 2 + 0] = l0 - lse;
    out[g * 2 + 1] = l1 - lse;
}

// ================= launch =================
extern "C" void kernel_launch(void* const* d_in, const int* in_sizes, int n_in,
                              void* d_out, int out_size) {
    const float* h   = (const float*)d_in[0];
    const int*   src = (const int*)d_in[1];
    const int*   dst = (const int*)d_in[2];
    const int*   gid = (const int*)d_in[3];
    const float* W1  = (const float*)d_in[4];
    const float* al1 = (const float*)d_in[5];
    const float* ar1 = (const float*)d_in[6];
    const float* b1  = (const float*)d_in[7];
    const float* W2  = (const float*)d_in[8];
    const float* al2 = (const float*)d_in[9];
    const float* ar2 = (const float*)d_in[10];
    const float* b2  = (const float*)d_in[11];
    const float* Wfc = (const float*)d_in[12];
    const float* bfc = (const float*)d_in[13];

    const int N = in_sizes[0] / D;
    const int E = in_sizes[1];

    float *bufA, *bufB, *el, *er, *ebuf, *acc, *gcnt;
    int *cnt, *rowptr, *cursor, *colv;
    cudaGetSymbolAddress((void**)&bufA,   g_bufA);
    cudaGetSymbolAddress((void**)&bufB,   g_bufB);
    cudaGetSymbolAddress((void**)&el,     g_el);
    cudaGetSymbolAddress((void**)&er,     g_er);
    cudaGetSymbolAddress((void**)&ebuf,   g_e);
    cudaGetSymbolAddress((void**)&cnt,    g_cnt);
    cudaGetSymbolAddress((void**)&rowptr, g_rowptr);
    cudaGetSymbolAddress((void**)&cursor, g_cursor);
    cudaGetSymbolAddress((void**)&colv,   g_col);
    cudaGetSymbolAddress((void**)&acc,    g_acc);
    cudaGetSymbolAddress((void**)&gcnt,   g_gcnt);

    cudaFuncSetAttribute(gemm_kernel, cudaFuncAttributeMaxDynamicSharedMemorySize,
                         GEMM_SMEM);

    const int TPB = 256;
    const int eBlocks     = (E + TPB - 1) / TPB;
    const int nWarpBlocks = (N * 32 + TPB - 1) / TPB;
    const int gemmBlocks  = (N + TILE_R - 1) / TILE_R;

    // ---- CSR build (shared by both layers) ----
    cudaMemsetAsync(cnt, 0, (size_t)N * sizeof(int), 0);
    hist_kernel<<<eBlocks, TPB>>>(dst, cnt, E);
    scan_kernel<<<1, 1024>>>(cnt, rowptr, cursor, N);
    scatter_kernel<<<eBlocks, TPB>>>(src, dst, cursor, colv, E);

    // ---- layer 1 ----
    gemm_kernel<<<gemmBlocks, TPB, GEMM_SMEM>>>(h, W1, nullptr, 0, al1, ar1,
                                                bufA, el, er, N);
    agg_kernel<<<nWarpBlocks, TPB>>>(rowptr, colv, el, er, bufA, ebuf, bufB, N,
                                     0, nullptr, nullptr, nullptr, nullptr, nullptr);

    // ---- layer 2 (pool fused into agg) ----
    gemm_kernel<<<gemmBlocks, TPB, GEMM_SMEM>>>(bufB, W2, b1, 1, al2, ar2,
                                                bufA, el, er, N);
    cudaMemsetAsync(acc, 0, NGRAPH * 2 * sizeof(float), 0);
    cudaMemsetAsync(gcnt, 0, NGRAPH * sizeof(float), 0);
    agg_kernel<<<nWarpBlocks, TPB>>>(rowptr, colv, el, er, bufA, ebuf, nullptr, N,
                                     1, b2, Wfc, gid, acc, gcnt);

    // ---- finalize ----
    finalize_kernel<<<1, 64>>>(acc, gcnt, bfc, (float*)d_out);
}

// round 4
// speedup vs baseline: 1.6353x; 1.0512x over previous
#include <cuda_runtime.h>
#include <cuda_fp16.h>
#include <math.h>

#define D       128
#define NMAX    100000
#define EMAX    1600000
#define NGRAPH  64
#define NEG_SLOPE 0.2f
#define TILE_R  128

typedef unsigned long long u64;

// ---------------- scratch (static device globals; no allocation) ------------
__device__ __half g_bufH[(size_t)NMAX * D];  // feat buffer in fp16 (25.6 MB)
__device__ float  g_bufB[(size_t)NMAX * D];  // layer-1 agg output fp32 (51.2 MB)
__device__ float  g_el[NMAX];
__device__ float  g_er[NMAX];
__device__ float  g_e[EMAX];                 // per-edge scratch (CSR order)
__device__ int    g_cnt[NMAX];
__device__ int    g_rowptr[NMAX + 1];
__device__ int    g_cursor[NMAX];
__device__ int    g_col[EMAX];               // src ids sorted by dst
__device__ float  g_acc[NGRAPH * 2];
__device__ float  g_gcnt[NGRAPH];

// ================= CSR build =================
__global__ void hist_kernel(const int* __restrict__ dst, int* __restrict__ cnt, int E) {
    int i = blockIdx.x * blockDim.x + threadIdx.x;
    if (i < E) atomicAdd(&cnt[dst[i]], 1);
}

__global__ void scan_kernel(const int* __restrict__ cnt, int* __restrict__ rowptr,
                            int* __restrict__ cursor, int N) {
    __shared__ int wsum[32];
    int t = threadIdx.x;
    int chunk = (N + 1023) >> 10;
    int b = t * chunk; if (b > N) b = N;
    int e = b + chunk; if (e > N) e = N;
    int sum = 0;
    for (int i = b; i < e; i++) sum += cnt[i];
    int lane = t & 31, w = t >> 5;
    int v = sum;
#pragma unroll
    for (int o = 1; o < 32; o <<= 1) {
        int u = __shfl_up_sync(0xffffffffu, v, o);
        if (lane >= o) v += u;
    }
    if (lane == 31) wsum[w] = v;
    __syncthreads();
    if (w == 0) {
        int x = wsum[lane];
#pragma unroll
        for (int o = 1; o < 32; o <<= 1) {
            int u = __shfl_up_sync(0xffffffffu, x, o);
            if (lane >= o) x += u;
        }
        wsum[lane] = x;
    }
    __syncthreads();
    int run = v - sum + (w > 0 ? wsum[w - 1] : 0);
    for (int i = b; i < e; i++) {
        rowptr[i] = run; cursor[i] = run;
        run += cnt[i];
    }
    if (b < N && e == N) rowptr[N] = run;
}

__global__ void scatter_kernel(const int* __restrict__ src, const int* __restrict__ dst,
                               int* __restrict__ cursor, int* __restrict__ col, int E) {
    int i = blockIdx.x * blockDim.x + threadIdx.x;
    if (i < E) {
        int p = atomicAdd(&cursor[dst[i]], 1);
        col[p] = src[i];
    }
}

// ====== GEMM: outH = half(act(X) @ W) ; fused el/er = out @ {al, ar} ========
// 512 thr, tile 128 rows x 128 cols. Thread owns 4 rows x 4 column PAIRS at
// columns 2p + {0,32,64,96} (p = tx&15) -> conflict-free LDS.64 of W, used
// directly as the f32x2 operand of fma.rn.f32x2.
#define GEMM_SMEM ((D * D + D * TILE_R) * (int)sizeof(float))

__global__ void __launch_bounds__(512, 1)
gemm_kernel(const float* __restrict__ X, const float* __restrict__ W,
            const float* __restrict__ preBias, int preRelu,
            const float* __restrict__ al, const float* __restrict__ ar,
            __half* __restrict__ outH, float* __restrict__ el,
            float* __restrict__ er, int N) {
    extern __shared__ float sm[];
    float* Ws = sm;            // [k][c] 128x128
    float* Xs = sm + D * D;    // [k][r] 128x128
    const int tx   = threadIdx.x;
    const int row0 = blockIdx.x * TILE_R;

    // stage W (8 float4 per thread, coalesced)
    for (int idx = tx * 4; idx < D * D; idx += 512 * 4)
        *(float4*)&Ws[idx] = *(const float4*)&W[idx];

    // stage X transposed: 4 threads per row, 32 k's each
    {
        int r    = tx >> 2;
        int k0   = (tx & 3) * 32;
        int grow = row0 + r;
        if (grow < N) {
            const float* xr = X + (size_t)grow * D + k0;
#pragma unroll
            for (int kk = 0; kk < 32; kk += 4) {
                float4 v = *(const float4*)&xr[kk];
                if (preRelu) {
                    float4 b = *(const float4*)&preBias[k0 + kk];
                    v.x = fmaxf(v.x + b.x, 0.f);
                    v.y = fmaxf(v.y + b.y, 0.f);
                    v.z = fmaxf(v.z + b.z, 0.f);
                    v.w = fmaxf(v.w + b.w, 0.f);
                }
                Xs[(k0 + kk + 0) * TILE_R + r] = v.x;
                Xs[(k0 + kk + 1) * TILE_R + r] = v.y;
                Xs[(k0 + kk + 2) * TILE_R + r] = v.z;
                Xs[(k0 + kk + 3) * TILE_R + r] = v.w;
            }
        } else {
#pragma unroll
            for (int kk = 0; kk < 32; kk++) Xs[(k0 + kk) * TILE_R + r] = 0.f;
        }
    }
    __syncthreads();

    const int p = tx & 15;    // column pair lane: cols 2p + {0,32,64,96}
    const int q = tx >> 4;    // rows q*4 .. q*4+3
    u64 acc[4][4];
#pragma unroll
    for (int i = 0; i < 4; i++)
#pragma unroll
        for (int j = 0; j < 4; j++) acc[i][j] = 0ull;

#pragma unroll 4
    for (int k = 0; k < D; k++) {
        float4 xa = *(const float4*)&Xs[k * TILE_R + q * 4];
        const u64* wrow = (const u64*)&Ws[k * D];
        u64 w0 = wrow[p], w1 = wrow[p + 16], w2 = wrow[p + 32], w3 = wrow[p + 48];
        u64 xp[4];
        asm("mov.b64 %0, {%1, %1};" : "=l"(xp[0]) : "f"(xa.x));
        asm("mov.b64 %0, {%1, %1};" : "=l"(xp[1]) : "f"(xa.y));
        asm("mov.b64 %0, {%1, %1};" : "=l"(xp[2]) : "f"(xa.z));
        asm("mov.b64 %0, {%1, %1};" : "=l"(xp[3]) : "f"(xa.w));
#pragma unroll
        for (int i = 0; i < 4; i++) {
            asm("fma.rn.f32x2 %0, %1, %2, %0;" : "+l"(acc[i][0]) : "l"(xp[i]), "l"(w0));
            asm("fma.rn.f32x2 %0, %1, %2, %0;" : "+l"(acc[i][1]) : "l"(xp[i]), "l"(w1));
            asm("fma.rn.f32x2 %0, %1, %2, %0;" : "+l"(acc[i][2]) : "l"(xp[i]), "l"(w2));
            asm("fma.rn.f32x2 %0, %1, %2, %0;" : "+l"(acc[i][3]) : "l"(xp[i]), "l"(w3));
        }
    }

    // epilogue: store half + fused el/er partial dots (reduce over 16 p-lanes)
    float2 la[4], ra[4];
#pragma unroll
    for (int t = 0; t < 4; t++) {
        la[t] = *(const float2*)&al[2 * p + 32 * t];
        ra[t] = *(const float2*)&ar[2 * p + 32 * t];
    }
#pragma unroll
    for (int i = 0; i < 4; i++) {
        int grow = row0 + q * 4 + i;
        float pl = 0.f, pr = 0.f;
        float o0, o1;
#pragma unroll
        for (int t = 0; t < 4; t++) {
            asm("mov.b64 {%0, %1}, %2;" : "=f"(o0), "=f"(o1) : "l"(acc[i][t]));
            pl += o0 * la[t].x + o1 * la[t].y;
            pr += o0 * ra[t].x + o1 * ra[t].y;
            if (grow < N)
                *(__half2*)&outH[(size_t)grow * D + 2 * p + 32 * t] =
                    __float22half2_rn(make_float2(o0, o1));
        }
#pragma unroll
        for (int o = 8; o; o >>= 1) {
            pl += __shfl_xor_sync(0xffffffffu, pl, o);
            pr += __shfl_xor_sync(0xffffffffu, pr, o);
        }
        if (p == 0 && grow < N) { el[grow] = pl; er[grow] = pr; }
    }
}

// ========== fused per-dst edge softmax + aggregation (warp per dst) =========
__device__ __forceinline__ void fma_half8(float& a0, float& a1, float& a2, float& a3,
                                          float w, uint2 u) {
    __half2 h0 = *reinterpret_cast<__half2*>(&u.x);
    __half2 h1 = *reinterpret_cast<__half2*>(&u.y);
    float2 f0 = __half22float2(h0);
    float2 f1 = __half22float2(h1);
    a0 = fmaf(w, f0.x, a0); a1 = fmaf(w, f0.y, a1);
    a2 = fmaf(w, f1.x, a2); a3 = fmaf(w, f1.y, a3);
}

__global__ void agg_kernel(const int* __restrict__ rowptr, const int* __restrict__ col,
                           const float* __restrict__ el, const float* __restrict__ er,
                           const __half* __restrict__ feat, float* __restrict__ ebuf,
                           float* __restrict__ out, int N, int doPool,
                           const float* __restrict__ b2, const float* __restrict__ Wfc,
                           const int* __restrict__ gid,
                           float* __restrict__ acc, float* __restrict__ gcnt) {
    int node = (blockIdx.x * blockDim.x + threadIdx.x) >> 5;
    int lane = threadIdx.x & 31;
    if (node >= N) return;
    int beg = rowptr[node], end = rowptr[node + 1];
    int deg = end - beg;
    float a0 = 0.f, a1 = 0.f, a2 = 0.f, a3 = 0.f;

    if (deg > 0) {
        float erd = er[node];
        if (deg <= 32) {
            // register fast path: one edge per lane, no ebuf traffic
            int   myi = 0;
            float v = -INFINITY;
            if (lane < deg) {
                myi = col[beg + lane];
                float t = el[myi] + erd;
                v = t > 0.f ? t : NEG_SLOPE * t;
            }
            float mx = v;
#pragma unroll
            for (int o = 16; o; o >>= 1)
                mx = fmaxf(mx, __shfl_xor_sync(0xffffffffu, mx, o));
            float mye = (lane < deg) ? __expf(v - mx) : 0.f;
            float s = mye;
#pragma unroll
            for (int o = 16; o; o >>= 1)
                s += __shfl_xor_sync(0xffffffffu, s, o);
            float inv = 1.0f / s;
            // weighted gather, 8 edges in flight (each edge row = 2 L2 lines)
            int j = 0;
            for (; j + 7 < deg; j += 8) {
                int   si[8]; float wi[8]; uint2 u[8];
#pragma unroll
                for (int t = 0; t < 8; t++) {
                    si[t] = __shfl_sync(0xffffffffu, myi, j + t);
                    wi[t] = __shfl_sync(0xffffffffu, mye, j + t) * inv;
                }
#pragma unroll
                for (int t = 0; t < 8; t++)
                    u[t] = *(const uint2*)(feat + (size_t)si[t] * D + lane * 4);
#pragma unroll
                for (int t = 0; t < 8; t++)
                    fma_half8(a0, a1, a2, a3, wi[t], u[t]);
            }
            for (; j + 3 < deg; j += 4) {
                int   si[4]; float wi[4]; uint2 u[4];
#pragma unroll
                for (int t = 0; t < 4; t++) {
                    si[t] = __shfl_sync(0xffffffffu, myi, j + t);
                    wi[t] = __shfl_sync(0xffffffffu, mye, j + t) * inv;
                }
#pragma unroll
                for (int t = 0; t < 4; t++)
                    u[t] = *(const uint2*)(feat + (size_t)si[t] * D + lane * 4);
#pragma unroll
                for (int t = 0; t < 4; t++)
                    fma_half8(a0, a1, a2, a3, wi[t], u[t]);
            }
            for (; j < deg; j++) {
                int   sA = __shfl_sync(0xffffffffu, myi, j);
                float wA = __shfl_sync(0xffffffffu, mye, j) * inv;
                uint2 uA = *(const uint2*)(feat + (size_t)sA * D + lane * 4);
                fma_half8(a0, a1, a2, a3, wA, uA);
            }
        } else {
            // general path via ebuf (rare: deg > 32)
            float mx = -INFINITY;
            for (int i = beg + lane; i < end; i += 32) {
                float v = el[col[i]] + erd;
                v = v > 0.f ? v : NEG_SLOPE * v;
                ebuf[i] = v;
                mx = fmaxf(mx, v);
            }
#pragma unroll
            for (int o = 16; o; o >>= 1)
                mx = fmaxf(mx, __shfl_xor_sync(0xffffffffu, mx, o));
            float s = 0.f;
            for (int i = beg + lane; i < end; i += 32) {
                float ex = __expf(ebuf[i] - mx);
                ebuf[i] = ex;
                s += ex;
            }
#pragma unroll
            for (int o = 16; o; o >>= 1)
                s += __shfl_xor_sync(0xffffffffu, s, o);
            float inv = 1.0f / s;
            for (int base = beg; base < end; base += 32) {
                int rem = end - base;
                int cnt = rem < 32 ? rem : 32;
                int mi = 0; float me = 0.f;
                if (lane < cnt) { mi = col[base + lane]; me = ebuf[base + lane]; }
                int j = 0;
                for (; j + 7 < cnt; j += 8) {
                    int   si[8]; float wi[8]; uint2 u[8];
#pragma unroll
                    for (int t = 0; t < 8; t++) {
                        si[t] = __shfl_sync(0xffffffffu, mi, j + t);
                        wi[t] = __shfl_sync(0xffffffffu, me, j + t) * inv;
                    }
#pragma unroll
                    for (int t = 0; t < 8; t++)
                        u[t] = *(const uint2*)(feat + (size_t)si[t] * D + lane * 4);
#pragma unroll
                    for (int t = 0; t < 8; t++)
                        fma_half8(a0, a1, a2, a3, wi[t], u[t]);
                }
                for (; j < cnt; j++) {
                    int   sA = __shfl_sync(0xffffffffu, mi, j);
                    float wA = __shfl_sync(0xffffffffu, me, j) * inv;
                    uint2 uA = *(const uint2*)(feat + (size_t)sA * D + lane * 4);
                    fma_half8(a0, a1, a2, a3, wA, uA);
                }
            }
        }
    }

    if (!doPool) {
        *(float4*)&out[(size_t)node * D + lane * 4] = make_float4(a0, a1, a2, a3);
    } else {
        float4 b = *(const float4*)&b2[lane * 4];
        float x0 = fmaxf(a0 + b.x, 0.f);
        float x1 = fmaxf(a1 + b.y, 0.f);
        float x2 = fmaxf(a2 + b.z, 0.f);
        float x3 = fmaxf(a3 + b.w, 0.f);
        float4 w01 = *(const float4*)&Wfc[lane * 8];
        float4 w23 = *(const float4*)&Wfc[lane * 8 + 4];
        float d0 = x0 * w01.x + x1 * w01.z + x2 * w23.x + x3 * w23.z;
        float d1 = x0 * w01.y + x1 * w01.w + x2 * w23.y + x3 * w23.w;
#pragma unroll
        for (int o = 16; o; o >>= 1) {
            d0 += __shfl_xor_sync(0xffffffffu, d0, o);
            d1 += __shfl_xor_sync(0xffffffffu, d1, o);
        }
        if (lane == 0) {
            int g = gid[node];
            atomicAdd(&acc[g * 2 + 0], d0);
            atomicAdd(&acc[g * 2 + 1], d1);
            atomicAdd(&gcnt[g], 1.f);
        }
    }
}

// ========== finalize: mean, +bfc, log_softmax ==========
__global__ void finalize_kernel(const float* __restrict__ acc,
                                const float* __restrict__ cnt,
                                const float* __restrict__ bfc,
                                float* __restrict__ out) {
    int g = threadIdx.x;
    if (g >= NGRAPH) return;
    float c  = fmaxf(cnt[g], 1.f);
    float l0 = acc[g * 2 + 0] / c + bfc[0];
    float l1 = acc[g * 2 + 1] / c + bfc[1];
    float mx  = fmaxf(l0, l1);
    float lse = mx + logf(expf(l0 - mx) + expf(l1 - mx));
    out[g * 2 + 0] = l0 - lse;
    out[g * 2 + 1] = l1 - lse;
}

// ================= launch =================
extern "C" void kernel_launch(void* const* d_in, const int* in_sizes, int n_in,
                              void* d_out, int out_size) {
    const float* h   = (const float*)d_in[0];
    const int*   src = (const int*)d_in[1];
    const int*   dst = (const int*)d_in[2];
    const int*   gid = (const int*)d_in[3];
    const float* W1  = (const float*)d_in[4];
    const float* al1 = (const float*)d_in[5];
    const float* ar1 = (const float*)d_in[6];
    const float* b1  = (const float*)d_in[7];
    const float* W2  = (const float*)d_in[8];
    const float* al2 = (const float*)d_in[9];
    const float* ar2 = (const float*)d_in[10];
    const float* b2  = (const float*)d_in[11];
    const float* Wfc = (const float*)d_in[12];
    const float* bfc = (const float*)d_in[13];

    const int N = in_sizes[0] / D;
    const int E = in_sizes[1];

    float *bufB, *el, *er, *ebuf, *acc, *gcnt;
    __half* bufH;
    int *cnt, *rowptr, *cursor, *colv;
    cudaGetSymbolAddress((void**)&bufH,   g_bufH);
    cudaGetSymbolAddress((void**)&bufB,   g_bufB);
    cudaGetSymbolAddress((void**)&el,     g_el);
    cudaGetSymbolAddress((void**)&er,     g_er);
    cudaGetSymbolAddress((void**)&ebuf,   g_e);
    cudaGetSymbolAddress((void**)&cnt,    g_cnt);
    cudaGetSymbolAddress((void**)&rowptr, g_rowptr);
    cudaGetSymbolAddress((void**)&cursor, g_cursor);
    cudaGetSymbolAddress((void**)&colv,   g_col);
    cudaGetSymbolAddress((void**)&acc,    g_acc);
    cudaGetSymbolAddress((void**)&gcnt,   g_gcnt);

    cudaFuncSetAttribute(gemm_kernel, cudaFuncAttributeMaxDynamicSharedMemorySize,
                         GEMM_SMEM);

    const int TPB = 256;
    const int eBlocks     = (E + TPB - 1) / TPB;
    const int nWarpBlocks = (N * 32 + TPB - 1) / TPB;
    const int gemmBlocks  = (N + TILE_R - 1) / TILE_R;

    // ---- CSR build (shared by both layers) ----
    cudaMemsetAsync(cnt, 0, (size_t)N * sizeof(int), 0);
    hist_kernel<<<eBlocks, TPB>>>(dst, cnt, E);
    scan_kernel<<<1, 1024>>>(cnt, rowptr, cursor, N);
    scatter_kernel<<<eBlocks, TPB>>>(src, dst, cursor, colv, E);

    // ---- layer 1 ----
    gemm_kernel<<<gemmBlocks, 512, GEMM_SMEM>>>(h, W1, nullptr, 0, al1, ar1,
                                                bufH, el, er, N);
    agg_kernel<<<nWarpBlocks, TPB>>>(rowptr, colv, el, er, bufH, ebuf, bufB, N,
                                     0, nullptr, nullptr, nullptr, nullptr, nullptr);

    // ---- layer 2 (pool fused into agg) ----
    gemm_kernel<<<gemmBlocks, 512, GEMM_SMEM>>>(bufB, W2, b1, 1, al2, ar2,
                                                bufH, el, er, N);
    cudaMemsetAsync(acc, 0, NGRAPH * 2 * sizeof(float), 0);
    cudaMemsetAsync(gcnt, 0, NGRAPH * sizeof(float), 0);
    agg_kernel<<<nWarpBlocks, TPB>>>(rowptr, colv, el, er, bufH, ebuf, nullptr, N,
                                     1, b2, Wfc, gid, acc, gcnt);

    // ---- finalize ----
    finalize_kernel<<<1, 64>>>(acc, gcnt, bfc, (float*)d_out);
}

// round 7
// speedup vs baseline: 1.9599x; 1.1985x over previous
#include <cuda_runtime.h>
#include <cuda_fp16.h>
#include <math.h>

#define D       128
#define NMAX    100000
#define EMAX    1600000
#define NGRAPH  64
#define NEG_SLOPE 0.2f
#define AS      136   // smem row stride in halves (128 + 8 pad)

typedef unsigned int  u32;
typedef unsigned long long u64;

// ---------------- scratch (static device globals; no allocation) ------------
__device__ __half g_bufH[(size_t)NMAX * D];  // layer feat fp16 (25.6 MB)
__device__ __half g_bufB[(size_t)NMAX * D];  // agg output fp16 (25.6 MB)
__device__ float  g_el[NMAX];
__device__ float  g_er[NMAX];
__device__ float  g_e[EMAX];                 // per-edge scratch (deg>32 path)
__device__ int    g_cnt[NMAX];
__device__ int    g_rowptr[NMAX + 1];
__device__ int    g_cursor[NMAX];
__device__ int    g_col[EMAX];               // src ids sorted by dst
__device__ float  g_acc[NGRAPH * 2];
__device__ float  g_gcnt[NGRAPH];

// ================= CSR build =================
__global__ void hist_kernel(const int* __restrict__ dst, int* __restrict__ cnt, int E) {
    int i = blockIdx.x * blockDim.x + threadIdx.x;
    if (i < E) atomicAdd(&cnt[dst[i]], 1);
}

__global__ void scan_kernel(const int* __restrict__ cnt, int* __restrict__ rowptr,
                            int* __restrict__ cursor, int N) {
    __shared__ int wsum[32];
    int t = threadIdx.x;
    int chunk = (N + 1023) >> 10;
    int b = t * chunk; if (b > N) b = N;
    int e = b + chunk; if (e > N) e = N;
    int sum = 0;
    for (int i = b; i < e; i++) sum += cnt[i];
    int lane = t & 31, w = t >> 5;
    int v = sum;
#pragma unroll
    for (int o = 1; o < 32; o <<= 1) {
        int u = __shfl_up_sync(0xffffffffu, v, o);
        if (lane >= o) v += u;
    }
    if (lane == 31) wsum[w] = v;
    __syncthreads();
    if (w == 0) {
        int x = wsum[lane];
#pragma unroll
        for (int o = 1; o < 32; o <<= 1) {
            int u = __shfl_up_sync(0xffffffffu, x, o);
            if (lane >= o) x += u;
        }
        wsum[lane] = x;
    }
    __syncthreads();
    int run = v - sum + (w > 0 ? wsum[w - 1] : 0);
    for (int i = b; i < e; i++) {
        rowptr[i] = run; cursor[i] = run;
        run += cnt[i];
    }
    if (b < N && e == N) rowptr[N] = run;
}

__global__ void scatter_kernel(const int* __restrict__ src, const int* __restrict__ dst,
                               int* __restrict__ cursor, int* __restrict__ col, int E) {
    int i = blockIdx.x * blockDim.x + threadIdx.x;
    if (i < E) {
        int p = atomicAdd(&cursor[dst[i]], 1);
        col[p] = src[i];
    }
}

// ====== HMMA GEMM: outH = half(act(X) @ W); fused el/er epilogue ============
// 512 thr, block tile 128x128, warp grid 4x4 (warp tile 32x32).
// mma.sync.m16n8k16 f16*f16 -> f32 accum, ldmatrix-fed, padded smem (AS=136).
#define GEMM_SMEM (2 * 128 * AS * 2 + 2 * 4 * 128 * 4)

__global__ void __launch_bounds__(512, 1)
gemm_hmma_kernel(const float* __restrict__ Xf, const __half* __restrict__ Xh,
                 const float* __restrict__ W,
                 const float* __restrict__ preBias, int preRelu,
                 const float* __restrict__ al, const float* __restrict__ ar,
                 __half* __restrict__ outH, float* __restrict__ el,
                 float* __restrict__ er, int N) {
    extern __shared__ char smraw[];
    __half* As = (__half*)smraw;                    // [128][AS]
    __half* Bs = As + 128 * AS;                     // [128][AS] (k rows, n cols)
    float* redEl = (float*)(Bs + 128 * AS);         // [4][128]
    float* redEr = redEl + 4 * 128;                 // [4][128]

    const int tx   = threadIdx.x;
    const int lane = tx & 31;
    const int warp = tx >> 5;
    const int row0 = blockIdx.x * 128;

    // ---- stage W -> Bs (fp32 -> fp16) ----
    {
        int k  = tx >> 2;
        int n0 = (tx & 3) * 32;
        const float* wr_ = W + k * D + n0;
#pragma unroll
        for (int j = 0; j < 32; j += 8) {
            float4 v0 = *(const float4*)&wr_[j];
            float4 v1 = *(const float4*)&wr_[j + 4];
            __half2 h0 = __floats2half2_rn(v0.x, v0.y);
            __half2 h1 = __floats2half2_rn(v0.z, v0.w);
            __half2 h2 = __floats2half2_rn(v1.x, v1.y);
            __half2 h3 = __floats2half2_rn(v1.z, v1.w);
            uint4 u = make_uint4(*(u32*)&h0, *(u32*)&h1, *(u32*)&h2, *(u32*)&h3);
            *(uint4*)&Bs[k * AS + n0 + j] = u;
        }
    }

    // ---- stage X -> As (fp32 or fp16 input, optional relu(x+bias)) ----
    {
        int r    = tx >> 2;
        int c0   = (tx & 3) * 32;
        int grow = row0 + r;
        if (grow < N) {
            if (Xf) {
                const float* xr_ = Xf + (size_t)grow * D + c0;
#pragma unroll
                for (int j = 0; j < 32; j += 8) {
                    float4 v0 = *(const float4*)&xr_[j];
                    float4 v1 = *(const float4*)&xr_[j + 4];
                    __half2 h0 = __floats2half2_rn(v0.x, v0.y);
                    __half2 h1 = __floats2half2_rn(v0.z, v0.w);
                    __half2 h2 = __floats2half2_rn(v1.x, v1.y);
                    __half2 h3 = __floats2half2_rn(v1.z, v1.w);
                    uint4 u = make_uint4(*(u32*)&h0, *(u32*)&h1, *(u32*)&h2, *(u32*)&h3);
                    *(uint4*)&As[r * AS + c0 + j] = u;
                }
            } else {
                const __half* xr_ = Xh + (size_t)grow * D + c0;
#pragma unroll
                for (int j = 0; j < 32; j += 8) {
                    uint4 raw = *(const uint4*)&xr_[j];
                    if (preRelu) {
                        const float* bb = preBias + c0 + j;
                        float2 f0 = __half22float2(*(__half2*)&raw.x);
                        float2 f1 = __half22float2(*(__half2*)&raw.y);
                        float2 f2 = __half22float2(*(__half2*)&raw.z);
                        float2 f3 = __half22float2(*(__half2*)&raw.w);
                        f0.x = fmaxf(f0.x + bb[0], 0.f); f0.y = fmaxf(f0.y + bb[1], 0.f);
                        f1.x = fmaxf(f1.x + bb[2], 0.f); f1.y = fmaxf(f1.y + bb[3], 0.f);
                        f2.x = fmaxf(f2.x + bb[4], 0.f); f2.y = fmaxf(f2.y + bb[5], 0.f);
                        f3.x = fmaxf(f3.x + bb[6], 0.f); f3.y = fmaxf(f3.y + bb[7], 0.f);
                        __half2 h0 = __floats2half2_rn(f0.x, f0.y);
                        __half2 h1 = __floats2half2_rn(f1.x, f1.y);
                        __half2 h2 = __floats2half2_rn(f2.x, f2.y);
                        __half2 h3 = __floats2half2_rn(f3.x, f3.y);
                        raw = make_uint4(*(u32*)&h0, *(u32*)&h1, *(u32*)&h2, *(u32*)&h3);
                    }
                    *(uint4*)&As[r * AS + c0 + j] = raw;
                }
            }
        } else {
#pragma unroll
            for (int j = 0; j < 32; j += 8)
                *(uint4*)&As[r * AS + c0 + j] = make_uint4(0, 0, 0, 0);
        }
    }
    __syncthreads();

    // ---- mainloop ----
    const int wr = warp >> 2;   // warp row 0..3  (rows wr*32 .. +31)
    const int wc = warp & 3;    // warp col 0..3  (cols wc*32 .. +31)
    float acc[2][4][4];
#pragma unroll
    for (int a = 0; a < 2; a++)
#pragma unroll
        for (int n = 0; n < 4; n++)
#pragma unroll
            for (int i = 0; i < 4; i++) acc[a][n][i] = 0.f;

    const u32 as_base = (u32)__cvta_generic_to_shared(As);
    const u32 bs_base = (u32)__cvta_generic_to_shared(Bs);
    const int g  = lane >> 3;      // ldmatrix lane group 0..3
    const int gi = lane & 7;

#pragma unroll
    for (int ks = 0; ks < 8; ks++) {
        const int k0 = ks * 16;
        // A frags: 2 row tiles (m16k16 each) via ldmatrix.x4
        u32 afr[2][4];
#pragma unroll
        for (int at = 0; at < 2; at++) {
            int arow = wr * 32 + at * 16 + gi + (g & 1) * 8;
            int acol = k0 + (g >> 1) * 8;
            u32 addr = as_base + (arow * AS + acol) * 2;
            asm volatile("ldmatrix.sync.aligned.m8n8.x4.shared.b16 {%0,%1,%2,%3}, [%4];"
                         : "=r"(afr[at][0]), "=r"(afr[at][1]),
                           "=r"(afr[at][2]), "=r"(afr[at][3]) : "r"(addr));
        }
        // B frags: 4 n8 tiles via 2x ldmatrix.x4.trans (each covers n16)
        u32 bfr[4][2];
#pragma unroll
        for (int h = 0; h < 2; h++) {
            int krow = k0 + gi + (g & 1) * 8;
            int ncol = wc * 32 + h * 16 + (g >> 1) * 8;
            u32 addr = bs_base + (krow * AS + ncol) * 2;
            u32 r0, r1, r2, r3;
            asm volatile("ldmatrix.sync.aligned.m8n8.x4.trans.shared.b16 {%0,%1,%2,%3}, [%4];"
                         : "=r"(r0), "=r"(r1), "=r"(r2), "=r"(r3) : "r"(addr));
            bfr[h * 2][0] = r0;     bfr[h * 2][1] = r1;
            bfr[h * 2 + 1][0] = r2; bfr[h * 2 + 1][1] = r3;
        }
#pragma unroll
        for (int at = 0; at < 2; at++)
#pragma unroll
            for (int nt = 0; nt < 4; nt++) {
                asm volatile(
                    "mma.sync.aligned.m16n8k16.row.col.f32.f16.f16.f32 "
                    "{%0,%1,%2,%3}, {%4,%5,%6,%7}, {%8,%9}, {%0,%1,%2,%3};"
                    : "+f"(acc[at][nt][0]), "+f"(acc[at][nt][1]),
                      "+f"(acc[at][nt][2]), "+f"(acc[at][nt][3])
                    : "r"(afr[at][0]), "r"(afr[at][1]), "r"(afr[at][2]), "r"(afr[at][3]),
                      "r"(bfr[nt][0]), "r"(bfr[nt][1]));
            }
    }

    // ---- epilogue: fp16 store + el/er partials ----
#pragma unroll
    for (int at = 0; at < 2; at++) {
        int r_lo = wr * 32 + at * 16 + (lane >> 2);
        int r_hi = r_lo + 8;
        float pll = 0.f, prl = 0.f, plh = 0.f, prh = 0.f;
#pragma unroll
        for (int nt = 0; nt < 4; nt++) {
            int colc = wc * 32 + nt * 8 + 2 * (lane & 3);
            float c0 = acc[at][nt][0], c1 = acc[at][nt][1];
            float c2 = acc[at][nt][2], c3 = acc[at][nt][3];
            float a0 = al[colc], a1 = al[colc + 1];
            float b0 = ar[colc], b1 = ar[colc + 1];
            pll += c0 * a0 + c1 * a1;  prl += c0 * b0 + c1 * b1;
            plh += c2 * a0 + c3 * a1;  prh += c2 * b0 + c3 * b1;
            if (row0 + r_lo < N) {
                __half2 h = __floats2half2_rn(c0, c1);
                *(__half2*)&outH[(size_t)(row0 + r_lo) * D + colc] = h;
            }
            if (row0 + r_hi < N) {
                __half2 h = __floats2half2_rn(c2, c3);
                *(__half2*)&outH[(size_t)(row0 + r_hi) * D + colc] = h;
            }
        }
#pragma unroll
        for (int o = 1; o <= 2; o <<= 1) {
            pll += __shfl_xor_sync(0xffffffffu, pll, o);
            prl += __shfl_xor_sync(0xffffffffu, prl, o);
            plh += __shfl_xor_sync(0xffffffffu, plh, o);
            prh += __shfl_xor_sync(0xffffffffu, prh, o);
        }
        if ((lane & 3) == 0) {
            redEl[wc * 128 + r_lo] = pll;  redEr[wc * 128 + r_lo] = prl;
            redEl[wc * 128 + r_hi] = plh;  redEr[wc * 128 + r_hi] = prh;
        }
    }
    __syncthreads();
    if (tx < 128 && row0 + tx < N) {
        float sl = redEl[tx] + redEl[128 + tx] + redEl[256 + tx] + redEl[384 + tx];
        float sr = redEr[tx] + redEr[128 + tx] + redEr[256 + tx] + redEr[384 + tx];
        el[row0 + tx] = sl;
        er[row0 + tx] = sr;
    }
}

// ========== fused per-dst edge softmax + aggregation (warp per dst) =========
__device__ __forceinline__ void fma_half8(float& a0, float& a1, float& a2, float& a3,
                                          float w, uint2 u) {
    float2 f0 = __half22float2(*reinterpret_cast<__half2*>(&u.x));
    float2 f1 = __half22float2(*reinterpret_cast<__half2*>(&u.y));
    a0 = fmaf(w, f0.x, a0); a1 = fmaf(w, f0.y, a1);
    a2 = fmaf(w, f1.x, a2); a3 = fmaf(w, f1.y, a3);
}

__global__ void agg_kernel(const int* __restrict__ rowptr, const int* __restrict__ col,
                           const float* __restrict__ el, const float* __restrict__ er,
                           const __half* __restrict__ feat, float* __restrict__ ebuf,
                           __half* __restrict__ out, int N, int doPool,
                           const float* __restrict__ b2, const float* __restrict__ Wfc,
                           const int* __restrict__ gid,
                           float* __restrict__ acc, float* __restrict__ gcnt) {
    int node = (blockIdx.x * blockDim.x + threadIdx.x) >> 5;
    int lane = threadIdx.x & 31;
    if (node >= N) return;
    int beg = rowptr[node], end = rowptr[node + 1];
    int deg = end - beg;
    float a0 = 0.f, a1 = 0.f, a2 = 0.f, a3 = 0.f;

    if (deg > 0) {
        float erd = er[node];
        if (deg <= 32) {
            int   myi = 0;
            float v = -INFINITY;
            if (lane < deg) {
                myi = col[beg + lane];
                float t = el[myi] + erd;
                v = t > 0.f ? t : NEG_SLOPE * t;
            }
            float mx = v;
#pragma unroll
            for (int o = 16; o; o >>= 1)
                mx = fmaxf(mx, __shfl_xor_sync(0xffffffffu, mx, o));
            float mye = (lane < deg) ? __expf(v - mx) : 0.f;
            float s = mye;
#pragma unroll
            for (int o = 16; o; o >>= 1)
                s += __shfl_xor_sync(0xffffffffu, s, o);
            float inv = 1.0f / s;
            int j = 0;
            for (; j + 7 < deg; j += 8) {
                int si[8]; float wi[8]; uint2 u[8];
#pragma unroll
                for (int t = 0; t < 8; t++) {
                    si[t] = __shfl_sync(0xffffffffu, myi, j + t);
                    wi[t] = __shfl_sync(0xffffffffu, mye, j + t) * inv;
                }
#pragma unroll
                for (int t = 0; t < 8; t++)
                    u[t] = *(const uint2*)(feat + (size_t)si[t] * D + lane * 4);
#pragma unroll
                for (int t = 0; t < 8; t++)
                    fma_half8(a0, a1, a2, a3, wi[t], u[t]);
            }
            for (; j + 3 < deg; j += 4) {
                int si[4]; float wi[4]; uint2 u[4];
#pragma unroll
                for (int t = 0; t < 4; t++) {
                    si[t] = __shfl_sync(0xffffffffu, myi, j + t);
                    wi[t] = __shfl_sync(0xffffffffu, mye, j + t) * inv;
                }
#pragma unroll
                for (int t = 0; t < 4; t++)
                    u[t] = *(const uint2*)(feat + (size_t)si[t] * D + lane * 4);
#pragma unroll
                for (int t = 0; t < 4; t++)
                    fma_half8(a0, a1, a2, a3, wi[t], u[t]);
            }
            for (; j < deg; j++) {
                int   sA = __shfl_sync(0xffffffffu, myi, j);
                float wA = __shfl_sync(0xffffffffu, mye, j) * inv;
                uint2 uA = *(const uint2*)(feat + (size_t)sA * D + lane * 4);
                fma_half8(a0, a1, a2, a3, wA, uA);
            }
        } else {
            float mx = -INFINITY;
            for (int i = beg + lane; i < end; i += 32) {
                float v = el[col[i]] + erd;
                v = v > 0.f ? v : NEG_SLOPE * v;
                ebuf[i] = v;
                mx = fmaxf(mx, v);
            }
#pragma unroll
            for (int o = 16; o; o >>= 1)
                mx = fmaxf(mx, __shfl_xor_sync(0xffffffffu, mx, o));
            float s = 0.f;
            for (int i = beg + lane; i < end; i += 32) {
                float ex = __expf(ebuf[i] - mx);
                ebuf[i] = ex;
                s += ex;
            }
#pragma unroll
            for (int o = 16; o; o >>= 1)
                s += __shfl_xor_sync(0xffffffffu, s, o);
            float inv = 1.0f / s;
            for (int base = beg; base < end; base += 32) {
                int rem = end - base;
                int cnt = rem < 32 ? rem : 32;
                int mi = 0; float me = 0.f;
                if (lane < cnt) { mi = col[base + lane]; me = ebuf[base + lane]; }
                int j = 0;
                for (; j + 7 < cnt; j += 8) {
                    int si[8]; float wi[8]; uint2 u[8];
#pragma unroll
                    for (int t = 0; t < 8; t++) {
                        si[t] = __shfl_sync(0xffffffffu, mi, j + t);
                        wi[t] = __shfl_sync(0xffffffffu, me, j + t) * inv;
                    }
#pragma unroll
                    for (int t = 0; t < 8; t++)
                        u[t] = *(const uint2*)(feat + (size_t)si[t] * D + lane * 4);
#pragma unroll
                    for (int t = 0; t < 8; t++)
                        fma_half8(a0, a1, a2, a3, wi[t], u[t]);
                }
                for (; j < cnt; j++) {
                    int   sA = __shfl_sync(0xffffffffu, mi, j);
                    float wA = __shfl_sync(0xffffffffu, me, j) * inv;
                    uint2 uA = *(const uint2*)(feat + (size_t)sA * D + lane * 4);
                    fma_half8(a0, a1, a2, a3, wA, uA);
                }
            }
        }
    }

    if (!doPool) {
        __half2 h01 = __floats2half2_rn(a0, a1);
        __half2 h23 = __floats2half2_rn(a2, a3);
        uint2 u; u.x = *(u32*)&h01; u.y = *(u32*)&h23;
        *(uint2*)&out[(size_t)node * D + lane * 4] = u;
    } else {
        float4 b = *(const float4*)&b2[lane * 4];
        float x0 = fmaxf(a0 + b.x, 0.f);
        float x1 = fmaxf(a1 + b.y, 0.f);
        float x2 = fmaxf(a2 + b.z, 0.f);
        float x3 = fmaxf(a3 + b.w, 0.f);
        float4 w01 = *(const float4*)&Wfc[lane * 8];
        float4 w23 = *(const float4*)&Wfc[lane * 8 + 4];
        float d0 = x0 * w01.x + x1 * w01.z + x2 * w23.x + x3 * w23.z;
        float d1 = x0 * w01.y + x1 * w01.w + x2 * w23.y + x3 * w23.w;
#pragma unroll
        for (int o = 16; o; o >>= 1) {
            d0 += __shfl_xor_sync(0xffffffffu, d0, o);
            d1 += __shfl_xor_sync(0xffffffffu, d1, o);
        }
        if (lane == 0) {
            int g = gid[node];
            atomicAdd(&acc[g * 2 + 0], d0);
            atomicAdd(&acc[g * 2 + 1], d1);
            atomicAdd(&gcnt[g], 1.f);
        }
    }
}

// ========== finalize: mean, +bfc, log_softmax ==========
__global__ void finalize_kernel(const float* __restrict__ acc,
                                const float* __restrict__ cnt,
                                const float* __restrict__ bfc,
                                float* __restrict__ out) {
    int g = threadIdx.x;
    if (g >= NGRAPH) return;
    float c  = fmaxf(cnt[g], 1.f);
    float l0 = acc[g * 2 + 0] / c + bfc[0];
    float l1 = acc[g * 2 + 1] / c + bfc[1];
    float mx  = fmaxf(l0, l1);
    float lse = mx + logf(expf(l0 - mx) + expf(l1 - mx));
    out[g * 2 + 0] = l0 - lse;
    out[g * 2 + 1] = l1 - lse;
}

// ================= launch =================
extern "C" void kernel_launch(void* const* d_in, const int* in_sizes, int n_in,
                              void* d_out, int out_size) {
    const float* h   = (const float*)d_in[0];
    const int*   src = (const int*)d_in[1];
    const int*   dst = (const int*)d_in[2];
    const int*   gid = (const int*)d_in[3];
    const float* W1  = (const float*)d_in[4];
    const float* al1 = (const float*)d_in[5];
    const float* ar1 = (const float*)d_in[6];
    const float* b1  = (const float*)d_in[7];
    const float* W2  = (const float*)d_in[8];
    const float* al2 = (const float*)d_in[9];
    const float* ar2 = (const float*)d_in[10];
    const float* b2  = (const float*)d_in[11];
    const float* Wfc = (const float*)d_in[12];
    const float* bfc = (const float*)d_in[13];

    const int N = in_sizes[0] / D;
    const int E = in_sizes[1];

    float *el, *er, *ebuf, *acc, *gcnt;
    __half *bufH, *bufB;
    int *cnt, *rowptr, *cursor, *colv;
    cudaGetSymbolAddress((void**)&bufH,   g_bufH);
    cudaGetSymbolAddress((void**)&bufB,   g_bufB);
    cudaGetSymbolAddress((void**)&el,     g_el);
    cudaGetSymbolAddress((void**)&er,     g_er);
    cudaGetSymbolAddress((void**)&ebuf,   g_e);
    cudaGetSymbolAddress((void**)&cnt,    g_cnt);
    cudaGetSymbolAddress((void**)&rowptr, g_rowptr);
    cudaGetSymbolAddress((void**)&cursor, g_cursor);
    cudaGetSymbolAddress((void**)&colv,   g_col);
    cudaGetSymbolAddress((void**)&acc,    g_acc);
    cudaGetSymbolAddress((void**)&gcnt,   g_gcnt);

    cudaFuncSetAttribute(gemm_hmma_kernel,
                         cudaFuncAttributeMaxDynamicSharedMemorySize, GEMM_SMEM);

    const int TPB = 256;
    const int eBlocks     = (E + TPB - 1) / TPB;
    const int nWarpBlocks = (N * 32 + TPB - 1) / TPB;
    const int gemmBlocks  = (N + 127) / 128;

    // ---- CSR build (shared by both layers) ----
    cudaMemsetAsync(cnt, 0, (size_t)N * sizeof(int), 0);
    hist_kernel<<<eBlocks, TPB>>>(dst, cnt, E);
    scan_kernel<<<1, 1024>>>(cnt, rowptr, cursor, N);
    scatter_kernel<<<eBlocks, TPB>>>(src, dst, cursor, colv, E);

    // ---- layer 1 ----
    gemm_hmma_kernel<<<gemmBlocks, 512, GEMM_SMEM>>>(h, nullptr, W1, nullptr, 0,
                                                     al1, ar1, bufH, el, er, N);
    agg_kernel<<<nWarpBlocks, TPB>>>(rowptr, colv, el, er, bufH, ebuf, bufB, N,
                                     0, nullptr, nullptr, nullptr, nullptr, nullptr);

    // ---- layer 2 (pool fused into agg) ----
    gemm_hmma_kernel<<<gemmBlocks, 512, GEMM_SMEM>>>(nullptr, bufB, W2, b1, 1,
                                                     al2, ar2, bufH, el, er, N);
    cudaMemsetAsync(acc, 0, NGRAPH * 2 * sizeof(float), 0);
    cudaMemsetAsync(gcnt, 0, NGRAPH * sizeof(float), 0);
    agg_kernel<<<nWarpBlocks, TPB>>>(rowptr, colv, el, er, bufH, ebuf, nullptr, N,
                                     1, b2, Wfc, gid, acc, gcnt);

    // ---- finalize ----
    finalize_kernel<<<1, 64>>>(acc, gcnt, bfc, (float*)d_out);
}